// round 1
// baseline (speedup 1.0000x reference)
#include <cuda_runtime.h>
#include <math_constants.h>

// WeightedChamferDistance: B=4, N=M=8192, D=3.
// out = mean_b( sum_n min_m d2 * w[b,n] ) + mean_b( sum_m min_n d2 )
//
// Strategy: per-thread point, scan all 8192 "others" in shared-memory tiles
// preprocessed as (-2x, -2y, -2z, |o|^2), two others packed per fma.rn.f32x2.
// Inner body per j-pair: 2x LDS.128 + 3x FFMA2 + 2x FMNMX.

#define BATCH 4
#define NPTS  8192            // N == M
#define TILE  2048            // others per shared tile (32 KB)
#define THREADS 256

__device__ float g_partials[2 * BATCH * (NPTS / THREADS)];   // 256 partials

__global__ __launch_bounds__(THREADS)
void chamfer_kernel(const float* __restrict__ src,
                    const float* __restrict__ tgt,
                    const float* __restrict__ w)
{
    // Tile layout per pair k (8 floats = 32 B):
    //  [0]=-2x0 [1]=-2x1 [2]=-2y0 [3]=-2y1 [4]=-2z0 [5]=-2z1 [6]=o2_0 [7]=o2_1
    __shared__ float s_tile[TILE * 4];
    __shared__ float s_red[THREADS];

    const int bx = blockIdx.x;
    const bool bwd = bx >= (BATCH * (NPTS / THREADS));     // second half: target->source
    const int lx = bwd ? bx - BATCH * (NPTS / THREADS) : bx;
    const int b  = lx >> 5;                                 // 32 blocks per batch
    const int pid = ((lx & 31) * THREADS) + threadIdx.x;    // point index in [0, NPTS)

    const float* pts = bwd ? tgt : src;
    const float* oth = bwd ? src : tgt;

    // Load this thread's point
    const float* pp = pts + ((size_t)b * NPTS + pid) * 3;
    const float px = pp[0], py = pp[1], pz = pp[2];
    const float p2 = px * px + py * py + pz * pz;

    // Duplicate source coords into packed f32x2 operands
    unsigned long long sxx, syy, szz;
    asm("mov.b64 %0,{%1,%1};" : "=l"(sxx) : "f"(px));
    asm("mov.b64 %0,{%1,%1};" : "=l"(syy) : "f"(py));
    asm("mov.b64 %0,{%1,%1};" : "=l"(szz) : "f"(pz));

    unsigned sbase;
    asm("{ .reg .u64 t; cvta.to.shared.u64 t, %1; cvt.u32.u64 %0, t; }"
        : "=r"(sbase) : "l"(s_tile));

    float m0 = CUDART_INF_F, m1 = CUDART_INF_F;

    const float* obase = oth + (size_t)b * NPTS * 3;

    for (int t = 0; t < NPTS; t += TILE) {
        __syncthreads();
        // Cooperative tile load + preprocess
        #pragma unroll
        for (int it = 0; it < TILE / THREADS; ++it) {
            const int idx = it * THREADS + threadIdx.x;
            const float* o = obase + (size_t)(t + idx) * 3;
            const float ox = o[0], oy = o[1], oz = o[2];
            const float o2 = ox * ox + oy * oy + oz * oz;
            float* bp = s_tile + (idx >> 1) * 8 + (idx & 1);
            bp[0] = -2.0f * ox;
            bp[2] = -2.0f * oy;
            bp[4] = -2.0f * oz;
            bp[6] = o2;
        }
        __syncthreads();

        // Main scan: TILE/2 packed pairs
        #pragma unroll 8
        for (int kk = 0; kk < TILE / 2; ++kk) {
            const unsigned a = sbase + kk * 32u;
            unsigned long long txp, typ, tzp, t2p, acc;
            asm("ld.shared.v2.u64 {%0,%1},[%2];"
                : "=l"(txp), "=l"(typ) : "r"(a));
            asm("ld.shared.v2.u64 {%0,%1},[%2];"
                : "=l"(tzp), "=l"(t2p) : "r"(a + 16u));
            asm("fma.rn.f32x2 %0,%1,%2,%3;"
                : "=l"(acc) : "l"(sxx), "l"(txp), "l"(t2p));
            asm("fma.rn.f32x2 %0,%1,%2,%3;"
                : "=l"(acc) : "l"(syy), "l"(typ), "l"(acc));
            asm("fma.rn.f32x2 %0,%1,%2,%3;"
                : "=l"(acc) : "l"(szz), "l"(tzp), "l"(acc));
            float lo, hi;
            asm("mov.b64 {%0,%1},%2;" : "=f"(lo), "=f"(hi) : "l"(acc));
            m0 = fminf(m0, lo);
            m1 = fminf(m1, hi);
        }
    }

    float d = p2 + fminf(m0, m1);                      // nearest-neighbor squared dist
    float c = bwd ? d : d * w[(size_t)b * NPTS + pid]; // fwd weighted, bwd unweighted

    // Deterministic block reduction
    s_red[threadIdx.x] = c;
    __syncthreads();
    #pragma unroll
    for (int s = THREADS / 2; s > 0; s >>= 1) {
        if (threadIdx.x < s) s_red[threadIdx.x] += s_red[threadIdx.x + s];
        __syncthreads();
    }
    if (threadIdx.x == 0) g_partials[bx] = s_red[0];
}

__global__ void finalize_kernel(float* __restrict__ out)
{
    __shared__ float s_red[256];
    s_red[threadIdx.x] = g_partials[threadIdx.x];
    __syncthreads();
    #pragma unroll
    for (int s = 128; s > 0; s >>= 1) {
        if (threadIdx.x < s) s_red[threadIdx.x] += s_red[threadIdx.x + s];
        __syncthreads();
    }
    if (threadIdx.x == 0) out[0] = s_red[0] * (1.0f / (float)BATCH);
}

extern "C" void kernel_launch(void* const* d_in, const int* in_sizes, int n_in,
                              void* d_out, int out_size)
{
    const float* src = (const float*)d_in[0];   // [B, N, 3]
    const float* tgt = (const float*)d_in[1];   // [B, M, 3]
    const float* w   = (const float*)d_in[2];   // [B, N]
    float* out = (float*)d_out;

    const int nblocks = 2 * BATCH * (NPTS / THREADS);   // 256
    chamfer_kernel<<<nblocks, THREADS>>>(src, tgt, w);
    finalize_kernel<<<1, 256>>>(out);
}

// round 2
// speedup vs baseline: 1.6046x; 1.6046x over previous
#include <cuda_runtime.h>
#include <math_constants.h>

// WeightedChamferDistance: B=4, N=M=8192, D=3.
// out = mean_b( sum_n min_m d2 * w[b,n] ) + mean_b( sum_m min_n d2 )
//
// Pass1: split the 8192-other scan into 8 chunks of 1024; each block handles
//        256 points (2 per thread, 128 threads) x 1 chunk, writes per-point
//        partial min(o2 - 2 p.o) + p2. Others preprocessed into shared as
//        packed pairs (-2x, -2y, -2z, |o|^2); fma.rn.f32x2 does 2 others/op.
// Pass2: min over 8 partials, weight the forward direction, block reduce.
// Pass3: final sum of 256 block sums, /BATCH.

#define BATCH   4
#define NPTS    8192
#define TILE    1024            // others per chunk (16 KB tile)
#define SPLITS  8               // NPTS / TILE
#define T1      128             // threads in pass1 block (2 points each)

__device__ float g_partial[2 * BATCH * NPTS * SPLITS];  // 2 MB
__device__ float g_sums[256];

__global__ __launch_bounds__(T1)
void chamfer_pass1(const float* __restrict__ src,
                   const float* __restrict__ tgt)
{
    // Tile layout per pair k (8 floats = 32 B):
    //  [0]=-2x0 [1]=-2x1 [2]=-2y0 [3]=-2y1 [4]=-2z0 [5]=-2z1 [6]=o2_0 [7]=o2_1
    __shared__ float s_tile[TILE * 4];

    const int bx    = blockIdx.x;
    const int split = bx & (SPLITS - 1);
    const int g     = bx >> 3;             // 0..255 point-group id
    const bool bwd  = g >= (BATCH * (NPTS / 256));
    const int lg    = g & 127;
    const int b     = lg >> 5;
    const int pg    = lg & 31;

    const float* pts = bwd ? tgt : src;
    const float* oth = bwd ? src : tgt;

    const int pidA = pg * 256 + threadIdx.x;
    const int pidB = pidA + T1;

    // Load this thread's two points
    const float* pa = pts + ((size_t)b * NPTS + pidA) * 3;
    const float* pb = pts + ((size_t)b * NPTS + pidB) * 3;
    const float ax = pa[0], ay = pa[1], az = pa[2];
    const float bxc = pb[0], byc = pb[1], bzc = pb[2];
    const float a2 = ax * ax + ay * ay + az * az;
    const float b2 = bxc * bxc + byc * byc + bzc * bzc;

    // Duplicate coords into packed f32x2 operands
    unsigned long long axx, ayy, azz, bxx, byy, bzz;
    asm("mov.b64 %0,{%1,%1};" : "=l"(axx) : "f"(ax));
    asm("mov.b64 %0,{%1,%1};" : "=l"(ayy) : "f"(ay));
    asm("mov.b64 %0,{%1,%1};" : "=l"(azz) : "f"(az));
    asm("mov.b64 %0,{%1,%1};" : "=l"(bxx) : "f"(bxc));
    asm("mov.b64 %0,{%1,%1};" : "=l"(byy) : "f"(byc));
    asm("mov.b64 %0,{%1,%1};" : "=l"(bzz) : "f"(bzc));

    unsigned sbase;
    asm("{ .reg .u64 t; cvta.to.shared.u64 t, %1; cvt.u32.u64 %0, t; }"
        : "=r"(sbase) : "l"(s_tile));

    // Cooperative tile load + preprocess for this chunk
    const float* obase = oth + ((size_t)b * NPTS + split * TILE) * 3;
    #pragma unroll
    for (int it = 0; it < TILE / T1; ++it) {
        const int idx = it * T1 + threadIdx.x;
        const float* o = obase + (size_t)idx * 3;
        const float ox = o[0], oy = o[1], oz = o[2];
        const float o2 = ox * ox + oy * oy + oz * oz;
        float* bp = s_tile + (idx >> 1) * 8 + (idx & 1);
        bp[0] = -2.0f * ox;
        bp[2] = -2.0f * oy;
        bp[4] = -2.0f * oz;
        bp[6] = o2;
    }
    __syncthreads();

    float m0a = CUDART_INF_F, m1a = CUDART_INF_F;
    float m0b = CUDART_INF_F, m1b = CUDART_INF_F;

    // Scan: TILE/2 packed pairs, two points per thread share each load
    #pragma unroll 8
    for (int kk = 0; kk < TILE / 2; ++kk) {
        const unsigned a = sbase + kk * 32u;
        unsigned long long txp, typ, tzp, t2p, accA, accB;
        asm("ld.shared.v2.u64 {%0,%1},[%2];"
            : "=l"(txp), "=l"(typ) : "r"(a));
        asm("ld.shared.v2.u64 {%0,%1},[%2];"
            : "=l"(tzp), "=l"(t2p) : "r"(a + 16u));
        asm("fma.rn.f32x2 %0,%1,%2,%3;" : "=l"(accA) : "l"(axx), "l"(txp), "l"(t2p));
        asm("fma.rn.f32x2 %0,%1,%2,%3;" : "=l"(accA) : "l"(ayy), "l"(typ), "l"(accA));
        asm("fma.rn.f32x2 %0,%1,%2,%3;" : "=l"(accA) : "l"(azz), "l"(tzp), "l"(accA));
        asm("fma.rn.f32x2 %0,%1,%2,%3;" : "=l"(accB) : "l"(bxx), "l"(txp), "l"(t2p));
        asm("fma.rn.f32x2 %0,%1,%2,%3;" : "=l"(accB) : "l"(byy), "l"(typ), "l"(accB));
        asm("fma.rn.f32x2 %0,%1,%2,%3;" : "=l"(accB) : "l"(bzz), "l"(tzp), "l"(accB));
        float loA, hiA, loB, hiB;
        asm("mov.b64 {%0,%1},%2;" : "=f"(loA), "=f"(hiA) : "l"(accA));
        asm("mov.b64 {%0,%1},%2;" : "=f"(loB), "=f"(hiB) : "l"(accB));
        m0a = fminf(m0a, loA);
        m1a = fminf(m1a, hiA);
        m0b = fminf(m0b, loB);
        m1b = fminf(m1b, hiB);
    }

    const int base = ((int)bwd * BATCH + b) * NPTS;
    g_partial[(size_t)(base + pidA) * SPLITS + split] = a2 + fminf(m0a, m1a);
    g_partial[(size_t)(base + pidB) * SPLITS + split] = b2 + fminf(m0b, m1b);
}

__global__ __launch_bounds__(256)
void chamfer_pass2(const float* __restrict__ w)
{
    __shared__ float s_red[256];

    const int q = blockIdx.x * 256 + threadIdx.x;   // 0 .. 65535
    const int bwd = q >> 15;                        // 0 = fwd (weighted)
    const int r   = q & 32767;
    const int b   = r >> 13;
    const int pid = r & (NPTS - 1);

    const float4* pp = (const float4*)(g_partial + (size_t)q * SPLITS);
    const float4 v0 = pp[0];
    const float4 v1 = pp[1];
    float m = fminf(fminf(fminf(v0.x, v0.y), fminf(v0.z, v0.w)),
                    fminf(fminf(v1.x, v1.y), fminf(v1.z, v1.w)));
    if (!bwd) m *= w[(size_t)b * NPTS + pid];

    s_red[threadIdx.x] = m;
    __syncthreads();
    #pragma unroll
    for (int s = 128; s > 0; s >>= 1) {
        if (threadIdx.x < s) s_red[threadIdx.x] += s_red[threadIdx.x + s];
        __syncthreads();
    }
    if (threadIdx.x == 0) g_sums[blockIdx.x] = s_red[0];
}

__global__ void chamfer_pass3(float* __restrict__ out)
{
    __shared__ float s_red[256];
    s_red[threadIdx.x] = g_sums[threadIdx.x];
    __syncthreads();
    #pragma unroll
    for (int s = 128; s > 0; s >>= 1) {
        if (threadIdx.x < s) s_red[threadIdx.x] += s_red[threadIdx.x + s];
        __syncthreads();
    }
    if (threadIdx.x == 0) out[0] = s_red[0] * (1.0f / (float)BATCH);
}

extern "C" void kernel_launch(void* const* d_in, const int* in_sizes, int n_in,
                              void* d_out, int out_size)
{
    const float* src = (const float*)d_in[0];   // [B, N, 3]
    const float* tgt = (const float*)d_in[1];   // [B, M, 3]
    const float* w   = (const float*)d_in[2];   // [B, N]
    float* out = (float*)d_out;

    // 2 dirs * 4 batches * 32 point-groups * 8 splits = 2048 blocks
    chamfer_pass1<<<2 * BATCH * (NPTS / 256) * SPLITS, T1>>>(src, tgt);
    chamfer_pass2<<<256, 256>>>(w);
    chamfer_pass3<<<1, 256>>>(out);
}

// round 3
// speedup vs baseline: 1.7774x; 1.1077x over previous
#include <cuda_runtime.h>
#include <math_constants.h>

// WeightedChamferDistance: B=4, N=M=8192, D=3.
// out = mean_b( sum_n min_m d2 * w[b,n] ) + mean_b( sum_m min_n d2 )
//
// Pass1: 1024 blocks; each block = 512 points (4/thread, 128 threads) x one
//        1024-other chunk. Others preprocessed into shared as packed pairs
//        (-2x, -2y, -2z, |o|^2); fma.rn.f32x2 = 2 others/op; 2 broadcast
//        LDS.128 per iter serve 8 evals (LSU was the R2 bottleneck at 74%).
// Pass2: min over 8 split-partials, weight fwd direction, block reduce.
// Pass3: final sum of 256 block sums, /BATCH.

#define BATCH   4
#define NPTS    8192
#define TILE    1024            // others per chunk (16 KB tile)
#define SPLITS  8               // NPTS / TILE
#define T1      128             // pass1 threads (4 points each)
#define PPB     512             // points per block

__device__ float g_partial[2 * BATCH * NPTS * SPLITS];  // 2 MB
__device__ float g_sums[256];

__global__ __launch_bounds__(T1)
void chamfer_pass1(const float* __restrict__ src,
                   const float* __restrict__ tgt)
{
    // Tile layout per pair k (8 floats = 32 B):
    //  [0]=-2x0 [1]=-2x1 [2]=-2y0 [3]=-2y1 [4]=-2z0 [5]=-2z1 [6]=o2_0 [7]=o2_1
    __shared__ float s_tile[TILE * 4];

    const int bx    = blockIdx.x;
    const int split = bx & (SPLITS - 1);
    const int g     = bx >> 3;                       // 0..127 point-group id
    const bool bwd  = g >= (BATCH * (NPTS / PPB));   // >= 64
    const int lg    = g & 63;
    const int b     = lg >> 4;
    const int pg    = lg & 15;

    const float* pts = bwd ? tgt : src;
    const float* oth = bwd ? src : tgt;

    const int pid0 = pg * PPB + threadIdx.x;         // +0,+128,+256,+384

    // Load this thread's four points; duplicate coords into packed operands
    unsigned long long cx[4], cy[4], cz[4];
    float p2[4];
    #pragma unroll
    for (int k = 0; k < 4; ++k) {
        const float* p = pts + ((size_t)b * NPTS + pid0 + k * T1) * 3;
        const float x = p[0], y = p[1], z = p[2];
        p2[k] = x * x + y * y + z * z;
        asm("mov.b64 %0,{%1,%1};" : "=l"(cx[k]) : "f"(x));
        asm("mov.b64 %0,{%1,%1};" : "=l"(cy[k]) : "f"(y));
        asm("mov.b64 %0,{%1,%1};" : "=l"(cz[k]) : "f"(z));
    }

    unsigned sbase;
    asm("{ .reg .u64 t; cvta.to.shared.u64 t, %1; cvt.u32.u64 %0, t; }"
        : "=r"(sbase) : "l"(s_tile));

    // Cooperative tile load + preprocess for this chunk
    const float* obase = oth + ((size_t)b * NPTS + split * TILE) * 3;
    #pragma unroll
    for (int it = 0; it < TILE / T1; ++it) {
        const int idx = it * T1 + threadIdx.x;
        const float* o = obase + (size_t)idx * 3;
        const float ox = o[0], oy = o[1], oz = o[2];
        const float o2 = ox * ox + oy * oy + oz * oz;
        float* bp = s_tile + (idx >> 1) * 8 + (idx & 1);
        bp[0] = -2.0f * ox;
        bp[2] = -2.0f * oy;
        bp[4] = -2.0f * oz;
        bp[6] = o2;
    }
    __syncthreads();

    float m0[4], m1[4];
    #pragma unroll
    for (int k = 0; k < 4; ++k) { m0[k] = CUDART_INF_F; m1[k] = CUDART_INF_F; }

    // Scan: TILE/2 packed pairs; 4 points share each pair of LDS.128
    #pragma unroll 4
    for (int kk = 0; kk < TILE / 2; ++kk) {
        const unsigned a = sbase + kk * 32u;
        unsigned long long txp, typ, tzp, t2p;
        asm("ld.shared.v2.u64 {%0,%1},[%2];" : "=l"(txp), "=l"(typ) : "r"(a));
        asm("ld.shared.v2.u64 {%0,%1},[%2];" : "=l"(tzp), "=l"(t2p) : "r"(a + 16u));
        #pragma unroll
        for (int k = 0; k < 4; ++k) {
            unsigned long long acc;
            asm("fma.rn.f32x2 %0,%1,%2,%3;" : "=l"(acc) : "l"(cx[k]), "l"(txp), "l"(t2p));
            asm("fma.rn.f32x2 %0,%1,%2,%3;" : "=l"(acc) : "l"(cy[k]), "l"(typ), "l"(acc));
            asm("fma.rn.f32x2 %0,%1,%2,%3;" : "=l"(acc) : "l"(cz[k]), "l"(tzp), "l"(acc));
            float lo, hi;
            asm("mov.b64 {%0,%1},%2;" : "=f"(lo), "=f"(hi) : "l"(acc));
            m0[k] = fminf(m0[k], lo);
            m1[k] = fminf(m1[k], hi);
        }
    }

    const int base = ((int)bwd * BATCH + b) * NPTS;
    #pragma unroll
    for (int k = 0; k < 4; ++k) {
        g_partial[(size_t)(base + pid0 + k * T1) * SPLITS + split] =
            p2[k] + fminf(m0[k], m1[k]);
    }
}

__global__ __launch_bounds__(256)
void chamfer_pass2(const float* __restrict__ w)
{
    __shared__ float s_red[256];

    const int q = blockIdx.x * 256 + threadIdx.x;   // 0 .. 65535
    const int bwd = q >> 15;                        // 0 = fwd (weighted)
    const int r   = q & 32767;
    const int b   = r >> 13;
    const int pid = r & (NPTS - 1);

    const float4* pp = (const float4*)(g_partial + (size_t)q * SPLITS);
    const float4 v0 = pp[0];
    const float4 v1 = pp[1];
    float m = fminf(fminf(fminf(v0.x, v0.y), fminf(v0.z, v0.w)),
                    fminf(fminf(v1.x, v1.y), fminf(v1.z, v1.w)));
    if (!bwd) m *= w[(size_t)b * NPTS + pid];

    s_red[threadIdx.x] = m;
    __syncthreads();
    #pragma unroll
    for (int s = 128; s > 0; s >>= 1) {
        if (threadIdx.x < s) s_red[threadIdx.x] += s_red[threadIdx.x + s];
        __syncthreads();
    }
    if (threadIdx.x == 0) g_sums[blockIdx.x] = s_red[0];
}

__global__ void chamfer_pass3(float* __restrict__ out)
{
    __shared__ float s_red[256];
    s_red[threadIdx.x] = g_sums[threadIdx.x];
    __syncthreads();
    #pragma unroll
    for (int s = 128; s > 0; s >>= 1) {
        if (threadIdx.x < s) s_red[threadIdx.x] += s_red[threadIdx.x + s];
        __syncthreads();
    }
    if (threadIdx.x == 0) out[0] = s_red[0] * (1.0f / (float)BATCH);
}

extern "C" void kernel_launch(void* const* d_in, const int* in_sizes, int n_in,
                              void* d_out, int out_size)
{
    const float* src = (const float*)d_in[0];   // [B, N, 3]
    const float* tgt = (const float*)d_in[1];   // [B, M, 3]
    const float* w   = (const float*)d_in[2];   // [B, N]
    float* out = (float*)d_out;

    // 2 dirs * 4 batches * 16 point-groups * 8 splits = 1024 blocks
    chamfer_pass1<<<2 * BATCH * (NPTS / PPB) * SPLITS, T1>>>(src, tgt);
    chamfer_pass2<<<256, 256>>>(w);
    chamfer_pass3<<<1, 256>>>(out);
}

// round 4
// speedup vs baseline: 1.8408x; 1.0357x over previous
#include <cuda_runtime.h>
#include <math_constants.h>

// WeightedChamferDistance: B=4, N=M=8192, D=3.
// out = mean_b( sum_n min_m d2 * w[b,n] ) + mean_b( sum_m min_n d2 )
//
// Pass1: 2048 blocks; each block = 512 points (4/thread, 128 threads) x one
//        512-other chunk. Others preprocessed in shared as packed pairs
//        (-2x,-2y,-2z,|o|^2); fma.rn.f32x2 = 2 others/instr (1.5 instr/eval,
//        the pipe roofline); next iteration's LDS.128 pair is prefetched into
//        registers so shared-mem latency never sits on the FMA chain.
// Pass2: min over 16 split-partials, weight fwd direction, block reduce.
// Pass3: final sum of 256 block sums, /BATCH.

#define BATCH   4
#define NPTS    8192
#define TILE    512             // others per chunk (8 KB tile)
#define SPLITS  16              // NPTS / TILE
#define T1      128             // pass1 threads (4 points each)
#define PPB     512             // points per block

__device__ float g_partial[2 * BATCH * NPTS * SPLITS];  // 4 MB
__device__ float g_sums[256];

__global__ __launch_bounds__(T1, 8)
void chamfer_pass1(const float* __restrict__ src,
                   const float* __restrict__ tgt)
{
    // Tile layout per pair k (8 floats = 32 B):
    //  [0]=-2x0 [1]=-2x1 [2]=-2y0 [3]=-2y1 [4]=-2z0 [5]=-2z1 [6]=o2_0 [7]=o2_1
    __shared__ float s_tile[TILE * 4 + 8];   // +8 floats: prefetch overread pad

    const int bx    = blockIdx.x;
    const int split = bx & (SPLITS - 1);
    const int g     = bx >> 4;                       // 0..127 point-group id
    const bool bwd  = g >= (BATCH * (NPTS / PPB));   // >= 64
    const int lg    = g & 63;
    const int b     = lg >> 4;
    const int pg    = lg & 15;

    const float* pts = bwd ? tgt : src;
    const float* oth = bwd ? src : tgt;

    const int pid0 = pg * PPB + threadIdx.x;         // +0,+128,+256,+384

    // Load this thread's four points; duplicate coords into packed operands
    unsigned long long cx[4], cy[4], cz[4];
    float p2[4];
    #pragma unroll
    for (int k = 0; k < 4; ++k) {
        const float* p = pts + ((size_t)b * NPTS + pid0 + k * T1) * 3;
        const float x = p[0], y = p[1], z = p[2];
        p2[k] = x * x + y * y + z * z;
        asm("mov.b64 %0,{%1,%1};" : "=l"(cx[k]) : "f"(x));
        asm("mov.b64 %0,{%1,%1};" : "=l"(cy[k]) : "f"(y));
        asm("mov.b64 %0,{%1,%1};" : "=l"(cz[k]) : "f"(z));
    }

    unsigned sbase;
    asm("{ .reg .u64 t; cvta.to.shared.u64 t, %1; cvt.u32.u64 %0, t; }"
        : "=r"(sbase) : "l"(s_tile));

    // Cooperative tile load + preprocess for this chunk
    const float* obase = oth + ((size_t)b * NPTS + split * TILE) * 3;
    #pragma unroll
    for (int it = 0; it < TILE / T1; ++it) {
        const int idx = it * T1 + threadIdx.x;
        const float* o = obase + (size_t)idx * 3;
        const float ox = o[0], oy = o[1], oz = o[2];
        const float o2 = ox * ox + oy * oy + oz * oz;
        float* bp = s_tile + (idx >> 1) * 8 + (idx & 1);
        bp[0] = -2.0f * ox;
        bp[2] = -2.0f * oy;
        bp[4] = -2.0f * oz;
        bp[6] = o2;
    }
    __syncthreads();

    float m0[4], m1[4];
    #pragma unroll
    for (int k = 0; k < 4; ++k) { m0[k] = CUDART_INF_F; m1[k] = CUDART_INF_F; }

    // Scan with register prefetch: iter kk computes on (txp..t2p) while
    // (ntx..nt2) for kk+1 is in flight. Last iter overreads into the pad.
    unsigned long long txp, typ, tzp, t2p;
    asm("ld.shared.v2.u64 {%0,%1},[%2];" : "=l"(txp), "=l"(typ) : "r"(sbase));
    asm("ld.shared.v2.u64 {%0,%1},[%2];" : "=l"(tzp), "=l"(t2p) : "r"(sbase + 16u));

    #pragma unroll 8
    for (int kk = 0; kk < TILE / 2; ++kk) {
        const unsigned a = sbase + kk * 32u + 32u;
        unsigned long long ntx, nty, ntz, nt2;
        asm("ld.shared.v2.u64 {%0,%1},[%2];" : "=l"(ntx), "=l"(nty) : "r"(a));
        asm("ld.shared.v2.u64 {%0,%1},[%2];" : "=l"(ntz), "=l"(nt2) : "r"(a + 16u));
        #pragma unroll
        for (int k = 0; k < 4; ++k) {
            unsigned long long acc;
            asm("fma.rn.f32x2 %0,%1,%2,%3;" : "=l"(acc) : "l"(cx[k]), "l"(txp), "l"(t2p));
            asm("fma.rn.f32x2 %0,%1,%2,%3;" : "=l"(acc) : "l"(cy[k]), "l"(typ), "l"(acc));
            asm("fma.rn.f32x2 %0,%1,%2,%3;" : "=l"(acc) : "l"(cz[k]), "l"(tzp), "l"(acc));
            float lo, hi;
            asm("mov.b64 {%0,%1},%2;" : "=f"(lo), "=f"(hi) : "l"(acc));
            m0[k] = fminf(m0[k], lo);
            m1[k] = fminf(m1[k], hi);
        }
        txp = ntx; typ = nty; tzp = ntz; t2p = nt2;
    }

    const int base = ((int)bwd * BATCH + b) * NPTS;
    #pragma unroll
    for (int k = 0; k < 4; ++k) {
        g_partial[(size_t)(base + pid0 + k * T1) * SPLITS + split] =
            p2[k] + fminf(m0[k], m1[k]);
    }
}

__global__ __launch_bounds__(256)
void chamfer_pass2(const float* __restrict__ w)
{
    __shared__ float s_red[256];

    const int q = blockIdx.x * 256 + threadIdx.x;   // 0 .. 65535
    const int bwd = q >> 15;                        // 0 = fwd (weighted)
    const int r   = q & 32767;
    const int b   = r >> 13;
    const int pid = r & (NPTS - 1);

    const float4* pp = (const float4*)(g_partial + (size_t)q * SPLITS);
    float m = CUDART_INF_F;
    #pragma unroll
    for (int i = 0; i < SPLITS / 4; ++i) {
        const float4 v = pp[i];
        m = fminf(m, fminf(fminf(v.x, v.y), fminf(v.z, v.w)));
    }
    if (!bwd) m *= w[(size_t)b * NPTS + pid];

    s_red[threadIdx.x] = m;
    __syncthreads();
    #pragma unroll
    for (int s = 128; s > 0; s >>= 1) {
        if (threadIdx.x < s) s_red[threadIdx.x] += s_red[threadIdx.x + s];
        __syncthreads();
    }
    if (threadIdx.x == 0) g_sums[blockIdx.x] = s_red[0];
}

__global__ void chamfer_pass3(float* __restrict__ out)
{
    __shared__ float s_red[256];
    s_red[threadIdx.x] = g_sums[threadIdx.x];
    __syncthreads();
    #pragma unroll
    for (int s = 128; s > 0; s >>= 1) {
        if (threadIdx.x < s) s_red[threadIdx.x] += s_red[threadIdx.x + s];
        __syncthreads();
    }
    if (threadIdx.x == 0) out[0] = s_red[0] * (1.0f / (float)BATCH);
}

extern "C" void kernel_launch(void* const* d_in, const int* in_sizes, int n_in,
                              void* d_out, int out_size)
{
    const float* src = (const float*)d_in[0];   // [B, N, 3]
    const float* tgt = (const float*)d_in[1];   // [B, M, 3]
    const float* w   = (const float*)d_in[2];   // [B, N]
    float* out = (float*)d_out;

    // 2 dirs * 4 batches * 16 point-groups * 16 splits = 2048 blocks
    chamfer_pass1<<<2 * BATCH * (NPTS / PPB) * SPLITS, T1>>>(src, tgt);
    chamfer_pass2<<<256, 256>>>(w);
    chamfer_pass3<<<1, 256>>>(out);
}